// round 15
// baseline (speedup 1.0000x reference)
#include <cuda_runtime.h>
#include <cstdint>

typedef unsigned long long ull;

// ---------------- problem constants ----------------
#define B_   4
#define F_   9
#define MP_  100
#define P_   12000
#define C_   64
#define NY_  400
#define NX_  400
#define NXO_ 4          // NX / POOL_W
#define NPTS (B_ * P_)  // 48000
#define NOUT (B_ * C_ * NY_ * NXO_) // 409600
#define EPSF 1e-3f

// main kernel tiling
#define TPB  128         // 4 warps: 2 point-groups x 2 channel-halves
#define NPB  32          // points per block (12000 % 32 == 0)
#define MPT  10          // mp per chunk
#define NCH  (MP_ / MPT) // 10 chunks
#define NBUF 3           // pipeline depth
#define FSTR 328         // f-stride in floats (10*32 + 8 pad -> bank = 8f+pt, conflict-free)
#define BUFSZ (F_ * FSTR)       // 2952 floats per chunk buffer
#define BUFB  (BUFSZ * 4)       // bytes (11808, 16B aligned)
#define CPOPS (F_ * MPT * NPB * 4 / 16)  // 720 cp.async 16B ops per chunk
#define CHF   (MPT * P_)        // float stride between chunks in gmem

// prep/init grid: block 0 packs weights, blocks 1..INIT_BLK init out
#define INIT_TPB 512
#define INIT_BLK (NOUT / 4 / INIT_TPB)   // 200

// ---------------- device scratch (no allocs allowed) ----------------
__device__ uint32_t g_w1hi[8 * 64];   // [f][ch] tf32 hi split of BN-folded w1 (f 0..7)
__device__ uint32_t g_w1mid[8 * 64];  // [f][ch] tf32 mid split (w to ~21 bits total)
__device__ uint32_t g_w18hi[64];      // f=8 row: tf32 hi split
__device__ uint32_t g_w18mid[64];     // f=8 row: tf32 mid split
__device__ float    g_b1f[64];        // folded bias 1
__device__ ull      g_w2p[32 * 64];   // [q][c] -> (w2'[2q][c], w2'[2q+1][c])
__device__ ull      g_b2p[32];

// ---------------- helpers ----------------
__device__ __forceinline__ ull ffma2(ull a, ull b, ull c) {
    ull d;
    asm("fma.rn.f32x2 %0, %1, %2, %3;" : "=l"(d) : "l"(a), "l"(b), "l"(c));
    return d;
}
__device__ __forceinline__ ull fpack(float x, float y) {
    ull r;
    asm("mov.b64 %0, {%1, %2};" : "=l"(r) : "f"(x), "f"(y));
    return r;
}
__device__ __forceinline__ ull fdup(float x) {
    ull r;
    asm("mov.b64 %0, {%1, %2};" : "=l"(r) : "f"(x), "f"(x));
    return r;
}
__device__ __forceinline__ void funpack(ull v, float& x, float& y) {
    asm("mov.b64 {%0, %1}, %2;" : "=f"(x), "=f"(y) : "l"(v));
}
__device__ __forceinline__ uint32_t tf32r(float x) {   // round-to-nearest tf32
    uint32_t r;
    asm("cvt.rna.tf32.f32 %0, %1;" : "=r"(r) : "f"(x));
    return r;
}
__device__ __forceinline__ void mma_tf32(float& d0, float& d1, float& d2, float& d3,
                                         uint32_t a0, uint32_t a1, uint32_t a2, uint32_t a3,
                                         uint32_t b0, uint32_t b1) {
    asm("mma.sync.aligned.m16n8k8.row.col.f32.tf32.tf32.f32 "
        "{%0,%1,%2,%3}, {%4,%5,%6,%7}, {%8,%9}, {%0,%1,%2,%3};"
        : "+f"(d0), "+f"(d1), "+f"(d2), "+f"(d3)
        : "r"(a0), "r"(a1), "r"(a2), "r"(a3), "r"(b0), "r"(b1));
}
__device__ __forceinline__ void mma_tf32_k4(float& d0, float& d1, float& d2, float& d3,
                                            uint32_t a0, uint32_t a1, uint32_t b0) {
    asm("mma.sync.aligned.m16n8k4.row.col.f32.tf32.tf32.f32 "
        "{%0,%1,%2,%3}, {%4,%5}, {%6}, {%0,%1,%2,%3};"
        : "+f"(d0), "+f"(d1), "+f"(d2), "+f"(d3)
        : "r"(a0), "r"(a1), "r"(b0));
}
__device__ __forceinline__ uint32_t smem_u32(const void* p) {
    return (uint32_t)__cvta_generic_to_shared(p);
}
__device__ __forceinline__ void cp16(uint32_t dst, const float* src) {
    asm volatile("cp.async.cg.shared.global [%0], [%1], 16;" :: "r"(dst), "l"(src));
}

// ---------------- prep + init (single launch) ----------------
// Block 0: BN-fold, tf32-split w1 (all 9 feature rows), pack w2.
// Blocks 1..INIT_BLK: init out = relu(b2') everywhere (every 100-cell pool
// window contains an empty canvas cell; P(full) ~ 1e-112 -> valid atomicMax
// floor).
__global__ void k_prep(const float* __restrict__ w1, const float* __restrict__ b1,
                       const float* __restrict__ g1, const float* __restrict__ be1,
                       const float* __restrict__ m1, const float* __restrict__ v1,
                       const float* __restrict__ w2, const float* __restrict__ b2,
                       const float* __restrict__ g2, const float* __restrict__ be2,
                       const float* __restrict__ m2, const float* __restrict__ v2,
                       float* __restrict__ out) {
    if (blockIdx.x == 0) {
        __shared__ float s1[C_], bb1[C_], s2[C_], bb2[C_];
        int t = threadIdx.x;
        if (t < C_) {
            float s = g1[t] * rsqrtf(v1[t] + EPSF);
            s1[t] = s;
            bb1[t] = b1[t] * s + be1[t] - m1[t] * s;
            float ss = g2[t] * rsqrtf(v2[t] + EPSF);
            s2[t] = ss;
            bb2[t] = b2[t] * ss + be2[t] - m2[t] * ss;
        }
        __syncthreads();
        // w1 splits for f 0..7: w = w1[c][f]*s1[c]; hi = tf32(w); mid = tf32(w-hi)
        for (int i = t; i < 8 * 64; i += INIT_TPB) {
            int f = i >> 6, c = i & 63;
            float w = w1[c * F_ + f] * s1[c];
            uint32_t hi = tf32r(w);
            g_w1hi[i]  = hi;
            g_w1mid[i] = tf32r(w - __uint_as_float(hi));
        }
        if (t < C_) {
            float w8 = w1[t * F_ + 8] * s1[t];
            uint32_t hi8 = tf32r(w8);
            g_w18hi[t]  = hi8;
            g_w18mid[t] = tf32r(w8 - __uint_as_float(hi8));
            g_b1f[t]    = bb1[t];
        }
        for (int i = t; i < 32 * 64; i += INIT_TPB) {
            int q = i / 64, c = i % 64;
            g_w2p[i] = fpack(w2[(2 * q) * C_ + c] * s2[2 * q],
                             w2[(2 * q + 1) * C_ + c] * s2[2 * q + 1]);
        }
        if (t < 32) g_b2p[t] = fpack(bb2[2 * t], bb2[2 * t + 1]);
    } else {
        int i = (blockIdx.x - 1) * INIT_TPB + threadIdx.x;  // float4 index
        int c = (i / NY_) & (C_ - 1);
        float ss = g2[c] * rsqrtf(v2[c] + EPSF);
        float zc = fmaxf(b2[c] * ss + be2[c] - m2[c] * ss, 0.0f);
        ((float4*)out)[i] = make_float4(zc, zc, zc, zc);
    }
}

// ---------------- main fused kernel (tensor-core stage 1) ----------------
// 4 warps; warp = (point-group of 16) x (channel-half of 32).
// Stage 1 per mpi, per 16x8 tile: d = mma_k4(f8: x8_hi duplicated in K-slots
// {0,1} against {w8_hi, w8_mid}) then two k8 mma (x_hi ⊗ w_hi, x_hi ⊗ w_mid
// for f0..7). All 9 features on the tensor pipe; residual = x's tf32
// rounding (~2^-11 -> rel_err ~1.2e-4). Max kept in 16 regs. 3-deep
// cp.async pipeline, one barrier per chunk; f-stride 328 keeps A-fragment
// LDS conflict-free.
__global__ void __launch_bounds__(TPB, 4) k_main(const float* __restrict__ x,
                                                 const int* __restrict__ coords,
                                                 float* __restrict__ out) {
    __shared__ float xs[NBUF][BUFSZ];
    __shared__ float feat[NPB][65];

    const int tid    = threadIdx.x;
    const int warp   = tid >> 5;
    const int lane   = tid & 31;
    const int g      = lane >> 2;      // groupID (fragment row base)
    const int tig    = lane & 3;       // thread-in-group (fragment col base)
    const int ptbase = (warp & 1) * 16;
    const int chbase = (warp >> 1) * 32;
    const int g0     = blockIdx.x * NPB;
    const int b      = g0 / P_;        // block never crosses batch
    const int pb     = g0 - b * P_;
    const bool tig01 = (tig < 2);      // A k4 slots 0,1 active

    // loop-invariant B fragments: k8 splits (f0..7) + k4 f8 fragment
    // k4 B layout: b = B[row=tig][col=g]; slots: 0 -> w8_hi, 1 -> w8_mid
    uint32_t bh0[4], bh1[4], bm0[4], bm1[4], b8[4];
    #pragma unroll
    for (int nt = 0; nt < 4; nt++) {
        int ch0 = chbase + nt * 8 + g;
        bh0[nt] = g_w1hi[tig * 64 + ch0];
        bh1[nt] = g_w1hi[(tig + 4) * 64 + ch0];
        bm0[nt] = g_w1mid[tig * 64 + ch0];
        bm1[nt] = g_w1mid[(tig + 4) * 64 + ch0];
        b8[nt]  = (tig == 0) ? g_w18hi[ch0] : ((tig == 1) ? g_w18mid[ch0] : 0u);
    }

    float m[16];
    #pragma unroll
    for (int i = 0; i < 16; i++) m[i] = -__int_as_float(0x7f800000);  // -inf

    const float* xb = x + (size_t)b * (F_ * MP_ * P_) + pb;

    // cp.async assignment: 720 16B ops/chunk, <=6 per thread
    // idx -> f = idx/80, mpi = (idx%80)/8, granule q = idx%8 (p = 4q)
    const uint32_t xs_base = smem_u32(&xs[0][0]);
    int      cp_soff[6];
    uint32_t cp_doff[6];
    bool     cp_on[6];
    #pragma unroll
    for (int k = 0; k < 6; k++) {
        int idx = tid + k * TPB;
        cp_on[k] = idx < CPOPS;
        int ii   = cp_on[k] ? idx : 0;
        int f    = ii / (MPT * 8);
        int r    = ii - f * (MPT * 8);
        int mpi  = r >> 3;
        int q    = r & 7;
        cp_soff[k] = f * (MP_ * P_) + mpi * P_ + q * 4;
        cp_doff[k] = (uint32_t)((f * FSTR + mpi * NPB + q * 4) * 4);
    }

    // prologue: prefetch chunks 0 and 1
    #pragma unroll
    for (int k = 0; k < 6; k++)
        if (cp_on[k]) cp16(xs_base + cp_doff[k], xb + cp_soff[k]);
    asm volatile("cp.async.commit_group;");
    #pragma unroll
    for (int k = 0; k < 6; k++)
        if (cp_on[k]) cp16(xs_base + BUFB + cp_doff[k], xb + cp_soff[k] + CHF);
    asm volatile("cp.async.commit_group;");

    int bufc = 0, bufn = 2;
    #pragma unroll 1
    for (int ch = 0; ch < NCH; ++ch) {
        if (ch < NCH - 1) asm volatile("cp.async.wait_group 1;");
        else              asm volatile("cp.async.wait_group 0;");
        __syncthreads();   // chunk ch visible; all done reading buf[bufn]

        if (ch + 2 < NCH) {
            uint32_t d = xs_base + (uint32_t)bufn * BUFB;
            const float* s = xb + (ch + 2) * CHF;
            #pragma unroll
            for (int k = 0; k < 6; k++)
                if (cp_on[k]) cp16(d + cp_doff[k], s + cp_soff[k]);
            asm volatile("cp.async.commit_group;");
        }

        #pragma unroll
        for (int mpi = 0; mpi < MPT; ++mpi) {
            const float* xc = &xs[bufc][mpi * NPB + ptbase];
            // k8 A fragment: A[pt][f], lane holds (g,tig),(g+8,tig),(g,tig+4),(g+8,tig+4)
            float a0f = xc[tig * FSTR + g];
            float a1f = xc[tig * FSTR + g + 8];
            float a2f = xc[(tig + 4) * FSTR + g];
            float a3f = xc[(tig + 4) * FSTR + g + 8];
            uint32_t ah0 = tf32r(a0f), ah1 = tf32r(a1f), ah2 = tf32r(a2f), ah3 = tf32r(a3f);
            // k4 A fragment (f8): slots 0,1 = x8_hi duplicated, slots 2,3 = 0
            uint32_t a8_0 = tig01 ? tf32r(xc[8 * FSTR + g])     : 0u;
            uint32_t a8_1 = tig01 ? tf32r(xc[8 * FSTR + g + 8]) : 0u;

            #pragma unroll
            for (int nt = 0; nt < 4; nt++) {
                float d0 = 0.f, d1 = 0.f, d2 = 0.f, d3 = 0.f;
                mma_tf32_k4(d0, d1, d2, d3, a8_0, a8_1, b8[nt]);
                mma_tf32(d0, d1, d2, d3, ah0, ah1, ah2, ah3, bh0[nt], bh1[nt]);
                mma_tf32(d0, d1, d2, d3, ah0, ah1, ah2, ah3, bm0[nt], bm1[nt]);
                m[nt * 4 + 0] = fmaxf(m[nt * 4 + 0], d0);
                m[nt * 4 + 1] = fmaxf(m[nt * 4 + 1], d1);
                m[nt * 4 + 2] = fmaxf(m[nt * 4 + 2], d2);
                m[nt * 4 + 3] = fmaxf(m[nt * 4 + 3], d3);
            }
        }
        bufc = (bufc == NBUF - 1) ? 0 : bufc + 1;
        bufn = (bufn == NBUF - 1) ? 0 : bufn + 1;
    }

    // bias + ReLU after the max; D-fragment -> feat[pt][ch]
    #pragma unroll
    for (int nt = 0; nt < 4; nt++) {
        #pragma unroll
        for (int k = 0; k < 4; k++) {
            int ch = chbase + nt * 8 + 2 * tig + (k & 1);
            int pt = ptbase + g + (k >> 1) * 8;
            feat[pt][ch] = fmaxf(m[nt * 4 + k] + g_b1f[ch], 0.0f);
        }
    }
    __syncthreads();

    // stage 2: 64->64 affine; lane = point, warp owns 8 ch-pairs (16 ch)
    const ull* __restrict__ w2g = g_w2p + warp * 8 * 64;
    ull acc[8];
    #pragma unroll
    for (int j = 0; j < 8; j++) acc[j] = g_b2p[warp * 8 + j];
    #pragma unroll 8
    for (int c = 0; c < C_; c++) {
        ull fd = fdup(feat[lane][c]);
        #pragma unroll
        for (int j = 0; j < 8; j++)
            acc[j] = ffma2(fd, w2g[j * 64 + c], acc[j]);
    }

    // scatter-max into pooled output (signed-int max == float max vs >=0 floor)
    const int  gp = g0 + lane;
    const int4 c4 = ((const int4*)coords)[gp];   // x=batch, z=y, w=x
    const int  xo = c4.w / 100;
    int* oi = (int*)out;
    #pragma unroll
    for (int j = 0; j < 8; j++) {
        float lo, hi;
        funpack(acc[j], lo, hi);
        int c0 = (warp * 8 + j) * 2;
        atomicMax(&oi[((c4.x * C_ + c0) * NY_ + c4.z) * NXO_ + xo], __float_as_int(lo));
        atomicMax(&oi[((c4.x * C_ + c0 + 1) * NY_ + c4.z) * NXO_ + xo], __float_as_int(hi));
    }
}

// ---------------- launch ----------------
extern "C" void kernel_launch(void* const* d_in, const int* in_sizes, int n_in,
                              void* d_out, int out_size) {
    const float* x      = (const float*)d_in[0];
    const int*   coords = (const int*)d_in[1];
    const float* w1  = (const float*)d_in[2];
    const float* b1  = (const float*)d_in[3];
    const float* g1  = (const float*)d_in[4];
    const float* be1 = (const float*)d_in[5];
    const float* m1  = (const float*)d_in[6];
    const float* v1  = (const float*)d_in[7];
    const float* w2  = (const float*)d_in[8];
    const float* b2  = (const float*)d_in[9];
    const float* g2  = (const float*)d_in[10];
    const float* be2 = (const float*)d_in[11];
    const float* m2  = (const float*)d_in[12];
    const float* v2  = (const float*)d_in[13];
    float* out = (float*)d_out;

    k_prep<<<1 + INIT_BLK, INIT_TPB>>>(w1, b1, g1, be1, m1, v1,
                                       w2, b2, g2, be2, m2, v2, out);
    k_main<<<NPTS / NPB, TPB>>>(x, coords, out);
}

// round 16
// speedup vs baseline: 1.1478x; 1.1478x over previous
#include <cuda_runtime.h>
#include <cstdint>

typedef unsigned long long ull;

// ---------------- problem constants ----------------
#define B_   4
#define F_   9
#define MP_  100
#define P_   12000
#define C_   64
#define NY_  400
#define NX_  400
#define NXO_ 4          // NX / POOL_W
#define NPTS (B_ * P_)  // 48000
#define NOUT (B_ * C_ * NY_ * NXO_) // 409600
#define EPSF 1e-3f

// main kernel tiling
#define TPB  128         // 4 warps: 2 point-groups x 2 channel-halves
#define NPB  32          // points per block (12000 % 32 == 0)
#define MPT  10          // mp per chunk
#define NCH  (MP_ / MPT) // 10 chunks
#define NBUF 3           // pipeline depth
#define FSTR 328         // f-stride in floats (10*32 + 8 pad -> bank = 8f+pt, conflict-free)
#define BUFSZ (F_ * FSTR)       // 2952 floats per chunk buffer
#define BUFB  (BUFSZ * 4)       // bytes (11808, 16B aligned)
#define CPOPS (F_ * MPT * NPB * 4 / 16)  // 720 cp.async 16B ops per chunk
#define CHF   (MPT * P_)        // float stride between chunks in gmem

// prep/init grid: block 0 packs weights, blocks 1..INIT_BLK init out
#define INIT_TPB 512
#define INIT_BLK (NOUT / 4 / INIT_TPB)   // 200

// ---------------- device scratch (no allocs allowed) ----------------
__device__ uint32_t g_w1hi[8 * 64];   // [f][ch] tf32 hi split of BN-folded w1 (f 0..7)
__device__ uint32_t g_w1mid[8 * 64];  // [f][ch] tf32 mid split; ROW 7 = tf32(w1[f=8])
__device__ float    g_b1f[64];        // folded bias 1
__device__ ull      g_w2p[32 * 64];   // [q][c] -> (w2'[2q][c], w2'[2q+1][c])
__device__ ull      g_b2p[32];

// ---------------- helpers ----------------
__device__ __forceinline__ ull ffma2(ull a, ull b, ull c) {
    ull d;
    asm("fma.rn.f32x2 %0, %1, %2, %3;" : "=l"(d) : "l"(a), "l"(b), "l"(c));
    return d;
}
__device__ __forceinline__ ull fpack(float x, float y) {
    ull r;
    asm("mov.b64 %0, {%1, %2};" : "=l"(r) : "f"(x), "f"(y));
    return r;
}
__device__ __forceinline__ ull fdup(float x) {
    ull r;
    asm("mov.b64 %0, {%1, %2};" : "=l"(r) : "f"(x), "f"(x));
    return r;
}
__device__ __forceinline__ void funpack(ull v, float& x, float& y) {
    asm("mov.b64 {%0, %1}, %2;" : "=f"(x), "=f"(y) : "l"(v));
}
__device__ __forceinline__ uint32_t tf32r(float x) {   // round-to-nearest tf32
    uint32_t r;
    asm("cvt.rna.tf32.f32 %0, %1;" : "=r"(r) : "f"(x));
    return r;
}
__device__ __forceinline__ void mma_tf32(float& d0, float& d1, float& d2, float& d3,
                                         uint32_t a0, uint32_t a1, uint32_t a2, uint32_t a3,
                                         uint32_t b0, uint32_t b1) {
    asm("mma.sync.aligned.m16n8k8.row.col.f32.tf32.tf32.f32 "
        "{%0,%1,%2,%3}, {%4,%5,%6,%7}, {%8,%9}, {%0,%1,%2,%3};"
        : "+f"(d0), "+f"(d1), "+f"(d2), "+f"(d3)
        : "r"(a0), "r"(a1), "r"(a2), "r"(a3), "r"(b0), "r"(b1));
}
__device__ __forceinline__ uint32_t smem_u32(const void* p) {
    return (uint32_t)__cvta_generic_to_shared(p);
}
__device__ __forceinline__ void cp16(uint32_t dst, const float* src) {
    asm volatile("cp.async.cg.shared.global [%0], [%1], 16;" :: "r"(dst), "l"(src));
}

// ---------------- prep + init (single launch) ----------------
// Block 0: BN-fold + tf32-split w1 + pack w2. Product-2 slot-7 trick:
// g_w1mid row 7 holds tf32(w1[f=8]) instead of f7's mid correction, so the
// second mma also computes the f8 term (with x8 substituted into slot 7 of
// the A fragment for tig==3 lanes). f7 keeps hi-only weights (~2^-11 w-err),
// f8 gets tf32 w and x -- total rel err ~1.3e-4, well under 1e-3.
// Blocks 1..INIT_BLK: init out = relu(b2') everywhere (every 100-cell pool
// window contains an empty canvas cell; P(full) ~ 1e-112 -> valid atomicMax
// floor).
__global__ void k_prep(const float* __restrict__ w1, const float* __restrict__ b1,
                       const float* __restrict__ g1, const float* __restrict__ be1,
                       const float* __restrict__ m1, const float* __restrict__ v1,
                       const float* __restrict__ w2, const float* __restrict__ b2,
                       const float* __restrict__ g2, const float* __restrict__ be2,
                       const float* __restrict__ m2, const float* __restrict__ v2,
                       float* __restrict__ out) {
    if (blockIdx.x == 0) {
        __shared__ float s1[C_], bb1[C_], s2[C_], bb2[C_];
        int t = threadIdx.x;
        if (t < C_) {
            float s = g1[t] * rsqrtf(v1[t] + EPSF);
            s1[t] = s;
            bb1[t] = b1[t] * s + be1[t] - m1[t] * s;
            float ss = g2[t] * rsqrtf(v2[t] + EPSF);
            s2[t] = ss;
            bb2[t] = b2[t] * ss + be2[t] - m2[t] * ss;
        }
        __syncthreads();
        // f 0..7: hi = tf32(w); mid = tf32(w - hi)  EXCEPT row 7 of mid,
        // which carries tf32(w[f=8]) (the slot-7 f8 path).
        for (int i = t; i < 8 * 64; i += INIT_TPB) {
            int f = i >> 6, c = i & 63;
            float w = w1[c * F_ + f] * s1[c];
            uint32_t hi = tf32r(w);
            g_w1hi[i] = hi;
            if (f == 7) {
                g_w1mid[i] = tf32r(w1[c * F_ + 8] * s1[c]);   // f8 weight
            } else {
                g_w1mid[i] = tf32r(w - __uint_as_float(hi));
            }
        }
        if (t < C_) g_b1f[t] = bb1[t];
        for (int i = t; i < 32 * 64; i += INIT_TPB) {
            int q = i / 64, c = i % 64;
            g_w2p[i] = fpack(w2[(2 * q) * C_ + c] * s2[2 * q],
                             w2[(2 * q + 1) * C_ + c] * s2[2 * q + 1]);
        }
        if (t < 32) g_b2p[t] = fpack(bb2[2 * t], bb2[2 * t + 1]);
    } else {
        int i = (blockIdx.x - 1) * INIT_TPB + threadIdx.x;  // float4 index
        int c = (i / NY_) & (C_ - 1);
        float ss = g2[c] * rsqrtf(v2[c] + EPSF);
        float zc = fmaxf(b2[c] * ss + be2[c] - m2[c] * ss, 0.0f);
        ((float4*)out)[i] = make_float4(zc, zc, zc, zc);
    }
}

// ---------------- main fused kernel (tensor-core stage 1) ----------------
// 4 warps; warp = (point-group of 16) x (channel-half of 32).
// Stage 1 per mpi, per 16x8 tile: two k8 mma —
//   product 1: x_hi(f0..7) ⊗ w_hi(f0..7)
//   product 2: slots 0..6 = x_hi ⊗ w_mid (f0..6); slot 7 = x8_hi ⊗ tf32(w8)
// (tig==3 lanes substitute x8 into their a2/a3 slot-7 positions). All 9
// features on the tensor pipe, no scalar fixup. Max kept in 16 regs.
// 3-deep cp.async pipeline, one barrier per chunk; f-stride 328 keeps
// A-fragment LDS conflict-free.
__global__ void __launch_bounds__(TPB, 4) k_main(const float* __restrict__ x,
                                                 const int* __restrict__ coords,
                                                 float* __restrict__ out) {
    __shared__ float xs[NBUF][BUFSZ];
    __shared__ float feat[NPB][65];

    const int tid    = threadIdx.x;
    const int warp   = tid >> 5;
    const int lane   = tid & 31;
    const int g      = lane >> 2;      // groupID (fragment row base)
    const int tig    = lane & 3;       // thread-in-group (fragment col base)
    const bool tig3  = (tig == 3);     // owns K-slot 7 (the f8 slot)
    const int ptbase = (warp & 1) * 16;
    const int chbase = (warp >> 1) * 32;
    const int g0     = blockIdx.x * NPB;
    const int b      = g0 / P_;        // block never crosses batch
    const int pb     = g0 - b * P_;

    // loop-invariant B fragments (w1 splits; mid row 7 = f8 weights)
    uint32_t bh0[4], bh1[4], bm0[4], bm1[4];
    #pragma unroll
    for (int nt = 0; nt < 4; nt++) {
        int ch0 = chbase + nt * 8 + g;
        bh0[nt] = g_w1hi[tig * 64 + ch0];
        bh1[nt] = g_w1hi[(tig + 4) * 64 + ch0];
        bm0[nt] = g_w1mid[tig * 64 + ch0];
        bm1[nt] = g_w1mid[(tig + 4) * 64 + ch0];
    }

    float m[16];
    #pragma unroll
    for (int i = 0; i < 16; i++) m[i] = -__int_as_float(0x7f800000);  // -inf

    const float* xb = x + (size_t)b * (F_ * MP_ * P_) + pb;

    // cp.async assignment: 720 16B ops/chunk, <=6 per thread
    // idx -> f = idx/80, mpi = (idx%80)/8, granule q = idx%8 (p = 4q)
    const uint32_t xs_base = smem_u32(&xs[0][0]);
    int      cp_soff[6];
    uint32_t cp_doff[6];
    bool     cp_on[6];
    #pragma unroll
    for (int k = 0; k < 6; k++) {
        int idx = tid + k * TPB;
        cp_on[k] = idx < CPOPS;
        int ii   = cp_on[k] ? idx : 0;
        int f    = ii / (MPT * 8);
        int r    = ii - f * (MPT * 8);
        int mpi  = r >> 3;
        int q    = r & 7;
        cp_soff[k] = f * (MP_ * P_) + mpi * P_ + q * 4;
        cp_doff[k] = (uint32_t)((f * FSTR + mpi * NPB + q * 4) * 4);
    }

    // prologue: prefetch chunks 0 and 1
    #pragma unroll
    for (int k = 0; k < 6; k++)
        if (cp_on[k]) cp16(xs_base + cp_doff[k], xb + cp_soff[k]);
    asm volatile("cp.async.commit_group;");
    #pragma unroll
    for (int k = 0; k < 6; k++)
        if (cp_on[k]) cp16(xs_base + BUFB + cp_doff[k], xb + cp_soff[k] + CHF);
    asm volatile("cp.async.commit_group;");

    int bufc = 0, bufn = 2;
    #pragma unroll 1
    for (int ch = 0; ch < NCH; ++ch) {
        if (ch < NCH - 1) asm volatile("cp.async.wait_group 1;");
        else              asm volatile("cp.async.wait_group 0;");
        __syncthreads();   // chunk ch visible; all done reading buf[bufn]

        if (ch + 2 < NCH) {
            uint32_t d = xs_base + (uint32_t)bufn * BUFB;
            const float* s = xb + (ch + 2) * CHF;
            #pragma unroll
            for (int k = 0; k < 6; k++)
                if (cp_on[k]) cp16(d + cp_doff[k], s + cp_soff[k]);
            asm volatile("cp.async.commit_group;");
        }

        #pragma unroll
        for (int mpi = 0; mpi < MPT; ++mpi) {
            const float* xc = &xs[bufc][mpi * NPB + ptbase];
            // k8 A fragment: A[pt][f]; lane holds (g,tig),(g+8,tig),(g,tig+4),(g+8,tig+4)
            float a0f = xc[tig * FSTR + g];
            float a1f = xc[tig * FSTR + g + 8];
            float a2f = xc[(tig + 4) * FSTR + g];
            float a3f = xc[(tig + 4) * FSTR + g + 8];
            uint32_t ah0 = tf32r(a0f), ah1 = tf32r(a1f), ah2 = tf32r(a2f), ah3 = tf32r(a3f);
            // product-2 A fragment: slot 7 (tig==3, a2/a3) carries x8 instead of x7
            uint32_t x8h0 = tf32r(xc[8 * FSTR + g]);
            uint32_t x8h1 = tf32r(xc[8 * FSTR + g + 8]);
            uint32_t am2 = tig3 ? x8h0 : ah2;
            uint32_t am3 = tig3 ? x8h1 : ah3;

            #pragma unroll
            for (int nt = 0; nt < 4; nt++) {
                float d0 = 0.f, d1 = 0.f, d2 = 0.f, d3 = 0.f;
                mma_tf32(d0, d1, d2, d3, ah0, ah1, ah2, ah3, bh0[nt], bh1[nt]);
                mma_tf32(d0, d1, d2, d3, ah0, ah1, am2, am3, bm0[nt], bm1[nt]);
                m[nt * 4 + 0] = fmaxf(m[nt * 4 + 0], d0);
                m[nt * 4 + 1] = fmaxf(m[nt * 4 + 1], d1);
                m[nt * 4 + 2] = fmaxf(m[nt * 4 + 2], d2);
                m[nt * 4 + 3] = fmaxf(m[nt * 4 + 3], d3);
            }
        }
        bufc = (bufc == NBUF - 1) ? 0 : bufc + 1;
        bufn = (bufn == NBUF - 1) ? 0 : bufn + 1;
    }

    // bias + ReLU after the max; D-fragment -> feat[pt][ch]
    #pragma unroll
    for (int nt = 0; nt < 4; nt++) {
        #pragma unroll
        for (int k = 0; k < 4; k++) {
            int ch = chbase + nt * 8 + 2 * tig + (k & 1);
            int pt = ptbase + g + (k >> 1) * 8;
            feat[pt][ch] = fmaxf(m[nt * 4 + k] + g_b1f[ch], 0.0f);
        }
    }
    __syncthreads();

    // stage 2: 64->64 affine; lane = point, warp owns 8 ch-pairs (16 ch)
    const ull* __restrict__ w2g = g_w2p + warp * 8 * 64;
    ull acc[8];
    #pragma unroll
    for (int j = 0; j < 8; j++) acc[j] = g_b2p[warp * 8 + j];
    #pragma unroll 8
    for (int c = 0; c < C_; c++) {
        ull fd = fdup(feat[lane][c]);
        #pragma unroll
        for (int j = 0; j < 8; j++)
            acc[j] = ffma2(fd, w2g[j * 64 + c], acc[j]);
    }

    // scatter-max into pooled output (signed-int max == float max vs >=0 floor)
    const int  gp = g0 + lane;
    const int4 c4 = ((const int4*)coords)[gp];   // x=batch, z=y, w=x
    const int  xo = c4.w / 100;
    int* oi = (int*)out;
    #pragma unroll
    for (int j = 0; j < 8; j++) {
        float lo, hi;
        funpack(acc[j], lo, hi);
        int c0 = (warp * 8 + j) * 2;
        atomicMax(&oi[((c4.x * C_ + c0) * NY_ + c4.z) * NXO_ + xo], __float_as_int(lo));
        atomicMax(&oi[((c4.x * C_ + c0 + 1) * NY_ + c4.z) * NXO_ + xo], __float_as_int(hi));
    }
}

// ---------------- launch ----------------
extern "C" void kernel_launch(void* const* d_in, const int* in_sizes, int n_in,
                              void* d_out, int out_size) {
    const float* x      = (const float*)d_in[0];
    const int*   coords = (const int*)d_in[1];
    const float* w1  = (const float*)d_in[2];
    const float* b1  = (const float*)d_in[3];
    const float* g1  = (const float*)d_in[4];
    const float* be1 = (const float*)d_in[5];
    const float* m1  = (const float*)d_in[6];
    const float* v1  = (const float*)d_in[7];
    const float* w2  = (const float*)d_in[8];
    const float* b2  = (const float*)d_in[9];
    const float* g2  = (const float*)d_in[10];
    const float* be2 = (const float*)d_in[11];
    const float* m2  = (const float*)d_in[12];
    const float* v2  = (const float*)d_in[13];
    float* out = (float*)d_out;

    k_prep<<<1 + INIT_BLK, INIT_TPB>>>(w1, b1, g1, be1, m1, v1,
                                       w2, b2, g2, be2, m2, v2, out);
    k_main<<<NPTS / NPB, TPB>>>(x, coords, out);
}

// round 17
// speedup vs baseline: 1.3709x; 1.1943x over previous
#include <cuda_runtime.h>
#include <cstdint>

typedef unsigned long long ull;

// ---------------- problem constants ----------------
#define B_   4
#define F_   9
#define MP_  100
#define P_   12000
#define C_   64
#define NY_  400
#define NX_  400
#define NXO_ 4          // NX / POOL_W
#define NPTS (B_ * P_)  // 48000
#define NOUT (B_ * C_ * NY_ * NXO_) // 409600
#define EPSF 1e-3f

// main kernel tiling
#define TPB  128         // 4 warps: 2 point-groups x 2 channel-halves
#define NPB  32          // points per block (12000 % 32 == 0)
#define MPT  10          // mp per chunk
#define NCH  (MP_ / MPT) // 10 chunks
#define NBUF 3           // pipeline depth
#define FSTR 328         // f-stride in floats (10*32 + 8 pad -> bank = 8f+pt, conflict-free)
#define BUFSZ (F_ * FSTR)       // 2952 floats per chunk buffer
#define BUFB  (BUFSZ * 4)       // bytes (11808, 16B aligned)
#define CPOPS (F_ * MPT * NPB * 4 / 16)  // 720 cp.async 16B ops per chunk
#define CHF   (MPT * P_)        // float stride between chunks in gmem

// prep/init grid: block 0 packs weights, blocks 1..INIT_BLK init out
#define INIT_TPB 512
#define INIT_BLK (NOUT / 4 / INIT_TPB)   // 200

// ---------------- device scratch (no allocs allowed) ----------------
__device__ uint32_t g_w1hi[8 * 64];   // [f][ch] tf32-rounded BN-folded w1 (f 0..7)
__device__ float    g_w1f8[64];       // f=8 row, full fp32 (scalar fixup path)
__device__ float    g_b1f[64];        // folded bias 1
__device__ ull      g_w2p[32 * 64];   // [q][c] -> (w2'[2q][c], w2'[2q+1][c])
__device__ ull      g_b2p[32];

// ---------------- helpers ----------------
__device__ __forceinline__ ull ffma2(ull a, ull b, ull c) {
    ull d;
    asm("fma.rn.f32x2 %0, %1, %2, %3;" : "=l"(d) : "l"(a), "l"(b), "l"(c));
    return d;
}
__device__ __forceinline__ ull fpack(float x, float y) {
    ull r;
    asm("mov.b64 %0, {%1, %2};" : "=l"(r) : "f"(x), "f"(y));
    return r;
}
__device__ __forceinline__ ull fdup(float x) {
    ull r;
    asm("mov.b64 %0, {%1, %2};" : "=l"(r) : "f"(x), "f"(x));
    return r;
}
__device__ __forceinline__ void funpack(ull v, float& x, float& y) {
    asm("mov.b64 {%0, %1}, %2;" : "=f"(x), "=f"(y) : "l"(v));
}
__device__ __forceinline__ uint32_t tf32r(float x) {   // round-to-nearest tf32
    uint32_t r;
    asm("cvt.rna.tf32.f32 %0, %1;" : "=r"(r) : "f"(x));
    return r;
}
__device__ __forceinline__ void mma_tf32(float& d0, float& d1, float& d2, float& d3,
                                         uint32_t a0, uint32_t a1, uint32_t a2, uint32_t a3,
                                         uint32_t b0, uint32_t b1) {
    asm("mma.sync.aligned.m16n8k8.row.col.f32.tf32.tf32.f32 "
        "{%0,%1,%2,%3}, {%4,%5,%6,%7}, {%8,%9}, {%0,%1,%2,%3};"
        : "+f"(d0), "+f"(d1), "+f"(d2), "+f"(d3)
        : "r"(a0), "r"(a1), "r"(a2), "r"(a3), "r"(b0), "r"(b1));
}
__device__ __forceinline__ uint32_t smem_u32(const void* p) {
    return (uint32_t)__cvta_generic_to_shared(p);
}
__device__ __forceinline__ void cp16(uint32_t dst, const float* src) {
    asm volatile("cp.async.cg.shared.global [%0], [%1], 16;" :: "r"(dst), "l"(src));
}

// ---------------- prep + init (single launch) ----------------
// Block 0: BN-fold, tf32-round w1 (f 0..7), pack w2. Blocks 1..INIT_BLK:
// init out = relu(b2') everywhere (every 100-cell pool window contains an
// empty canvas cell; P(full) ~ 1e-112 -> valid atomicMax floor).
__global__ void k_prep(const float* __restrict__ w1, const float* __restrict__ b1,
                       const float* __restrict__ g1, const float* __restrict__ be1,
                       const float* __restrict__ m1, const float* __restrict__ v1,
                       const float* __restrict__ w2, const float* __restrict__ b2,
                       const float* __restrict__ g2, const float* __restrict__ be2,
                       const float* __restrict__ m2, const float* __restrict__ v2,
                       float* __restrict__ out) {
    if (blockIdx.x == 0) {
        __shared__ float s1[C_], bb1[C_], s2[C_], bb2[C_];
        int t = threadIdx.x;
        if (t < C_) {
            float s = g1[t] * rsqrtf(v1[t] + EPSF);
            s1[t] = s;
            bb1[t] = b1[t] * s + be1[t] - m1[t] * s;
            float ss = g2[t] * rsqrtf(v2[t] + EPSF);
            s2[t] = ss;
            bb2[t] = b2[t] * ss + be2[t] - m2[t] * ss;
        }
        __syncthreads();
        // w1 for f 0..7: single tf32 rounding (x is also tf32-rounded in the
        // kernel; calibrated error model -> rel_err ~1.6e-4, margin vs 1e-3)
        for (int i = t; i < 8 * 64; i += INIT_TPB) {
            int f = i >> 6, c = i & 63;
            g_w1hi[i] = tf32r(w1[c * F_ + f] * s1[c]);
        }
        if (t < C_) {
            g_w1f8[t] = w1[t * F_ + 8] * s1[t];
            g_b1f[t]  = bb1[t];
        }
        for (int i = t; i < 32 * 64; i += INIT_TPB) {
            int q = i / 64, c = i % 64;
            g_w2p[i] = fpack(w2[(2 * q) * C_ + c] * s2[2 * q],
                             w2[(2 * q + 1) * C_ + c] * s2[2 * q + 1]);
        }
        if (t < 32) g_b2p[t] = fpack(bb2[2 * t], bb2[2 * t + 1]);
    } else {
        int i = (blockIdx.x - 1) * INIT_TPB + threadIdx.x;  // float4 index
        int c = (i / NY_) & (C_ - 1);
        float ss = g2[c] * rsqrtf(v2[c] + EPSF);
        float zc = fmaxf(b2[c] * ss + be2[c] - m2[c] * ss, 0.0f);
        ((float4*)out)[i] = make_float4(zc, zc, zc, zc);
    }
}

// ---------------- main fused kernel (tensor-core stage 1) ----------------
// 4 warps; warp = (point-group of 16) x (channel-half of 32).
// Stage 1 per mpi: D[16pt x 8ch] tiles via ONE tf32 mma (x_hi ⊗ w_hi,
// single product; calibrated error: x-rounding 1.1e-4 + w-rounding -> ~1.6e-4
// total, 6x under threshold) + scalar f=8 FFMA fixup in full fp32.
// Max kept in 16 regs. 3-deep cp.async pipeline, one barrier per chunk;
// f-stride 328 keeps A-fragment LDS conflict-free.
__global__ void __launch_bounds__(TPB, 4) k_main(const float* __restrict__ x,
                                                 const int* __restrict__ coords,
                                                 float* __restrict__ out) {
    __shared__ float xs[NBUF][BUFSZ];
    __shared__ float feat[NPB][65];

    const int tid    = threadIdx.x;
    const int warp   = tid >> 5;
    const int lane   = tid & 31;
    const int g      = lane >> 2;      // groupID (fragment row base)
    const int tig    = lane & 3;       // thread-in-group (fragment col base)
    const int ptbase = (warp & 1) * 16;
    const int chbase = (warp >> 1) * 32;
    const int g0     = blockIdx.x * NPB;
    const int b      = g0 / P_;        // block never crosses batch
    const int pb     = g0 - b * P_;

    // loop-invariant B fragments (tf32 w1) + f8 scalar weights
    uint32_t bh0[4], bh1[4];
    float    w8a[4], w8b[4];
    #pragma unroll
    for (int nt = 0; nt < 4; nt++) {
        int ch0 = chbase + nt * 8 + g;
        bh0[nt] = g_w1hi[tig * 64 + ch0];
        bh1[nt] = g_w1hi[(tig + 4) * 64 + ch0];
        int cw  = chbase + nt * 8 + 2 * tig;
        w8a[nt] = g_w1f8[cw];
        w8b[nt] = g_w1f8[cw + 1];
    }

    float m[16];
    #pragma unroll
    for (int i = 0; i < 16; i++) m[i] = -__int_as_float(0x7f800000);  // -inf

    const float* xb = x + (size_t)b * (F_ * MP_ * P_) + pb;

    // cp.async assignment: 720 16B ops/chunk, <=6 per thread
    // idx -> f = idx/80, mpi = (idx%80)/8, granule q = idx%8 (p = 4q)
    const uint32_t xs_base = smem_u32(&xs[0][0]);
    int      cp_soff[6];
    uint32_t cp_doff[6];
    bool     cp_on[6];
    #pragma unroll
    for (int k = 0; k < 6; k++) {
        int idx = tid + k * TPB;
        cp_on[k] = idx < CPOPS;
        int ii   = cp_on[k] ? idx : 0;
        int f    = ii / (MPT * 8);
        int r    = ii - f * (MPT * 8);
        int mpi  = r >> 3;
        int q    = r & 7;
        cp_soff[k] = f * (MP_ * P_) + mpi * P_ + q * 4;
        cp_doff[k] = (uint32_t)((f * FSTR + mpi * NPB + q * 4) * 4);
    }

    // prologue: prefetch chunks 0 and 1
    #pragma unroll
    for (int k = 0; k < 6; k++)
        if (cp_on[k]) cp16(xs_base + cp_doff[k], xb + cp_soff[k]);
    asm volatile("cp.async.commit_group;");
    #pragma unroll
    for (int k = 0; k < 6; k++)
        if (cp_on[k]) cp16(xs_base + BUFB + cp_doff[k], xb + cp_soff[k] + CHF);
    asm volatile("cp.async.commit_group;");

    int bufc = 0, bufn = 2;
    #pragma unroll 1
    for (int ch = 0; ch < NCH; ++ch) {
        if (ch < NCH - 1) asm volatile("cp.async.wait_group 1;");
        else              asm volatile("cp.async.wait_group 0;");
        __syncthreads();   // chunk ch visible; all done reading buf[bufn]

        if (ch + 2 < NCH) {
            uint32_t d = xs_base + (uint32_t)bufn * BUFB;
            const float* s = xb + (ch + 2) * CHF;
            #pragma unroll
            for (int k = 0; k < 6; k++)
                if (cp_on[k]) cp16(d + cp_doff[k], s + cp_soff[k]);
            asm volatile("cp.async.commit_group;");
        }

        #pragma unroll
        for (int mpi = 0; mpi < MPT; ++mpi) {
            const float* xc = &xs[bufc][mpi * NPB + ptbase];
            // A fragment: A[pt][f], lane holds (g,tig),(g+8,tig),(g,tig+4),(g+8,tig+4)
            float a0f = xc[tig * FSTR + g];
            float a1f = xc[tig * FSTR + g + 8];
            float a2f = xc[(tig + 4) * FSTR + g];
            float a3f = xc[(tig + 4) * FSTR + g + 8];
            float x80 = xc[8 * FSTR + g];        // f=8, broadcast across tig
            float x81 = xc[8 * FSTR + g + 8];
            uint32_t ah0 = tf32r(a0f), ah1 = tf32r(a1f), ah2 = tf32r(a2f), ah3 = tf32r(a3f);

            #pragma unroll
            for (int nt = 0; nt < 4; nt++) {
                float d0 = 0.f, d1 = 0.f, d2 = 0.f, d3 = 0.f;
                mma_tf32(d0, d1, d2, d3, ah0, ah1, ah2, ah3, bh0[nt], bh1[nt]);
                d0 = fmaf(x80, w8a[nt], d0);
                d1 = fmaf(x80, w8b[nt], d1);
                d2 = fmaf(x81, w8a[nt], d2);
                d3 = fmaf(x81, w8b[nt], d3);
                m[nt * 4 + 0] = fmaxf(m[nt * 4 + 0], d0);
                m[nt * 4 + 1] = fmaxf(m[nt * 4 + 1], d1);
                m[nt * 4 + 2] = fmaxf(m[nt * 4 + 2], d2);
                m[nt * 4 + 3] = fmaxf(m[nt * 4 + 3], d3);
            }
        }
        bufc = (bufc == NBUF - 1) ? 0 : bufc + 1;
        bufn = (bufn == NBUF - 1) ? 0 : bufn + 1;
    }

    // bias + ReLU after the max; D-fragment -> feat[pt][ch]
    #pragma unroll
    for (int nt = 0; nt < 4; nt++) {
        #pragma unroll
        for (int k = 0; k < 4; k++) {
            int ch = chbase + nt * 8 + 2 * tig + (k & 1);
            int pt = ptbase + g + (k >> 1) * 8;
            feat[pt][ch] = fmaxf(m[nt * 4 + k] + g_b1f[ch], 0.0f);
        }
    }
    __syncthreads();

    // stage 2: 64->64 affine; lane = point, warp owns 8 ch-pairs (16 ch)
    const ull* __restrict__ w2g = g_w2p + warp * 8 * 64;
    ull acc[8];
    #pragma unroll
    for (int j = 0; j < 8; j++) acc[j] = g_b2p[warp * 8 + j];
    #pragma unroll 8
    for (int c = 0; c < C_; c++) {
        ull fd = fdup(feat[lane][c]);
        #pragma unroll
        for (int j = 0; j < 8; j++)
            acc[j] = ffma2(fd, w2g[j * 64 + c], acc[j]);
    }

    // scatter-max into pooled output (signed-int max == float max vs >=0 floor)
    const int  gp = g0 + lane;
    const int4 c4 = ((const int4*)coords)[gp];   // x=batch, z=y, w=x
    const int  xo = c4.w / 100;
    int* oi = (int*)out;
    #pragma unroll
    for (int j = 0; j < 8; j++) {
        float lo, hi;
        funpack(acc[j], lo, hi);
        int c0 = (warp * 8 + j) * 2;
        atomicMax(&oi[((c4.x * C_ + c0) * NY_ + c4.z) * NXO_ + xo], __float_as_int(lo));
        atomicMax(&oi[((c4.x * C_ + c0 + 1) * NY_ + c4.z) * NXO_ + xo], __float_as_int(hi));
    }
}

// ---------------- launch ----------------
extern "C" void kernel_launch(void* const* d_in, const int* in_sizes, int n_in,
                              void* d_out, int out_size) {
    const float* x      = (const float*)d_in[0];
    const int*   coords = (const int*)d_in[1];
    const float* w1  = (const float*)d_in[2];
    const float* b1  = (const float*)d_in[3];
    const float* g1  = (const float*)d_in[4];
    const float* be1 = (const float*)d_in[5];
    const float* m1  = (const float*)d_in[6];
    const float* v1  = (const float*)d_in[7];
    const float* w2  = (const float*)d_in[8];
    const float* b2  = (const float*)d_in[9];
    const float* g2  = (const float*)d_in[10];
    const float* be2 = (const float*)d_in[11];
    const float* m2  = (const float*)d_in[12];
    const float* v2  = (const float*)d_in[13];
    float* out = (float*)d_out;

    k_prep<<<1 + INIT_BLK, INIT_TPB>>>(w1, b1, g1, be1, m1, v1,
                                       w2, b2, g2, be2, m2, v2, out);
    k_main<<<NPTS / NPB, TPB>>>(x, coords, out);
}